// round 17
// baseline (speedup 1.0000x reference)
#include <cuda_runtime.h>
#include <cuda_bf16.h>
#include <cstdint>

// ---------------------------------------------------------------------------
// BiLSTM: B=32, T=512, I=512, H=512, gates=4H=2048, out (32,512,1024) fp32
//
// Phase A: gx = x @ Wx^T + bx. 128x128 tile, 8x8 micro-tile, K-tile 8,
//          double-buffered smem, f32x2 packed FMA (proven round-6 version).
// Phase B: persistent scan, 2 dirs x 64 blocks x 512 threads.
//          Warp-autonomous k-sixteenths + flag-gated staging (round-12 PASS)
//          + NEW: two-stage parallel reduction (512-thread stage-1 folds the
//          16 warp-partials to 2; 128-thread finalize adds the halves) and
//          out[] stores deferred past the flag publish.
// ---------------------------------------------------------------------------

#define Bsz 32
#define Tsz 512
#define Isz 512
#define Hsz 512
#define G4  2048

#define JPB 8          // hidden units per block
#define NBLK_DIR 64    // blocks per direction
#define WJ 4100        // per-j stride in w_s floats (16B mod 128B j-spread)

__device__ float g_gx[(size_t)Bsz * Tsz * G4];
__device__ float g_h[2][2][Hsz * Bsz];             // [dir][parity][j*32 + b]
__device__ __align__(128) unsigned g_pflag[2][NBLK_DIR][32];  // [dir][sub][0]

// ---- packed f32x2 helpers --------------------------------------------------
__device__ __forceinline__ unsigned long long fma2(unsigned long long a,
                                                   unsigned long long b,
                                                   unsigned long long c) {
    unsigned long long d;
    asm("fma.rn.f32x2 %0, %1, %2, %3;" : "=l"(d) : "l"(a), "l"(b), "l"(c));
    return d;
}
__device__ __forceinline__ unsigned long long add2(unsigned long long a,
                                                   unsigned long long b) {
    unsigned long long d;
    asm("add.rn.f32x2 %0, %1, %2;" : "=l"(d) : "l"(a), "l"(b));
    return d;
}
__device__ __forceinline__ unsigned long long pack2(float lo, float hi) {
    unsigned long long r;
    asm("mov.b64 %0, {%1, %2};" : "=l"(r) : "f"(lo), "f"(hi));
    return r;
}
__device__ __forceinline__ float2 unpack2(unsigned long long v) {
    float2 r;
    asm("mov.b64 {%0, %1}, %2;" : "=f"(r.x), "=f"(r.y) : "l"(v));
    return r;
}
__device__ __forceinline__ unsigned ld_acquire_gpu(const unsigned* p) {
    unsigned v;
    asm volatile("ld.acquire.gpu.global.u32 %0, [%1];" : "=r"(v) : "l"(p));
    return v;
}
__device__ __forceinline__ void st_relaxed_gpu(unsigned* p, unsigned v) {
    asm volatile("st.relaxed.gpu.global.u32 [%0], %1;" :: "l"(p), "r"(v));
}
__device__ __forceinline__ float fast_sigmoid(float x) {
    return __fdividef(1.0f, 1.0f + __expf(-x));
}
__device__ __forceinline__ float fast_tanh(float x) {
    return 1.0f - 2.0f * __fdividef(1.0f, __expf(2.0f * x) + 1.0f);
}

// ---------------------------------------------------------------------------
// Phase A: gx = x @ Wx^T + bx  (proven round-6 SIMT version)
// ---------------------------------------------------------------------------
__global__ __launch_bounds__(256, 2) void gemm_gx(const float* __restrict__ A,
                                                  const float* __restrict__ W,
                                                  const float* __restrict__ bx) {
    __shared__ __align__(16) float As[2][8][132];
    __shared__ __align__(16) float Bs[2][8][132];

    const int bm = blockIdx.y * 128;
    const int bn = blockIdx.x * 128;
    const int tid = threadIdx.x;
    const int lrow = tid >> 1;
    const int lkh = (tid & 1) * 4;
    const int ty = tid >> 4;
    const int tx = tid & 15;
    const int m0 = ty * 8;
    const int n0 = tx * 8;

    const float* Aptr = A + (size_t)(bm + lrow) * Isz + lkh;
    const float* Wptr = W + (size_t)(bn + lrow) * Isz + lkh;

    {
        float4 a = *(const float4*)Aptr;
        float4 w = *(const float4*)Wptr;
        As[0][lkh + 0][lrow] = a.x;
        As[0][lkh + 1][lrow] = a.y;
        As[0][lkh + 2][lrow] = a.z;
        As[0][lkh + 3][lrow] = a.w;
        Bs[0][lkh + 0][lrow] = w.x;
        Bs[0][lkh + 1][lrow] = w.y;
        Bs[0][lkh + 2][lrow] = w.z;
        Bs[0][lkh + 3][lrow] = w.w;
    }
    __syncthreads();

    unsigned long long acc[8][4];
#pragma unroll
    for (int i = 0; i < 8; i++)
#pragma unroll
        for (int q = 0; q < 4; q++) acc[i][q] = 0ull;

    int cur = 0;
    for (int kt = 1; kt <= 64; kt++) {
        float4 an = make_float4(0.f, 0.f, 0.f, 0.f);
        float4 wn = make_float4(0.f, 0.f, 0.f, 0.f);
        if (kt < 64) {
            an = *(const float4*)(Aptr + kt * 8);
            wn = *(const float4*)(Wptr + kt * 8);
        }
#pragma unroll
        for (int k = 0; k < 8; k++) {
            float4 aLo = *(const float4*)&As[cur][k][m0];
            float4 aHi = *(const float4*)&As[cur][k][m0 + 4];
            ulonglong2 bLo = *(const ulonglong2*)&Bs[cur][k][n0];
            ulonglong2 bHi = *(const ulonglong2*)&Bs[cur][k][n0 + 4];
            float am[8] = {aLo.x, aLo.y, aLo.z, aLo.w,
                           aHi.x, aHi.y, aHi.z, aHi.w};
#pragma unroll
            for (int mm = 0; mm < 8; mm++) {
                unsigned long long ad = pack2(am[mm], am[mm]);
                acc[mm][0] = fma2(bLo.x, ad, acc[mm][0]);
                acc[mm][1] = fma2(bLo.y, ad, acc[mm][1]);
                acc[mm][2] = fma2(bHi.x, ad, acc[mm][2]);
                acc[mm][3] = fma2(bHi.y, ad, acc[mm][3]);
            }
        }
        if (kt < 64) {
            int nxt = cur ^ 1;
            As[nxt][lkh + 0][lrow] = an.x;
            As[nxt][lkh + 1][lrow] = an.y;
            As[nxt][lkh + 2][lrow] = an.z;
            As[nxt][lkh + 3][lrow] = an.w;
            Bs[nxt][lkh + 0][lrow] = wn.x;
            Bs[nxt][lkh + 1][lrow] = wn.y;
            Bs[nxt][lkh + 2][lrow] = wn.z;
            Bs[nxt][lkh + 3][lrow] = wn.w;
        }
        __syncthreads();
        cur ^= 1;
    }

    float4 bxLo = *(const float4*)&bx[bn + n0];
    float4 bxHi = *(const float4*)&bx[bn + n0 + 4];
#pragma unroll
    for (int mm = 0; mm < 8; mm++) {
        float2 p0 = unpack2(acc[mm][0]);
        float2 p1 = unpack2(acc[mm][1]);
        float2 p2 = unpack2(acc[mm][2]);
        float2 p3 = unpack2(acc[mm][3]);
        float4 r0 = make_float4(p0.x + bxLo.x, p0.y + bxLo.y,
                                p1.x + bxLo.z, p1.y + bxLo.w);
        float4 r1 = make_float4(p2.x + bxHi.x, p2.y + bxHi.y,
                                p3.x + bxHi.z, p3.y + bxHi.w);
        float* dst = &g_gx[(size_t)(bm + m0 + mm) * G4 + bn + n0];
        *(float4*)dst = r0;
        *(float4*)(dst + 4) = r1;
    }
}

// ---------------------------------------------------------------------------
// Phase B scan (round-12 base + two-stage reduction + deferred out stores).
// Partial layout per warp region w (1024 floats = 256 ull2 slots):
//   ull2 slot index = (g*2 + bph)*32 + lane, g=gate, bph=batch-quad half.
// Stage-1: thread (s1 = tid>>6, l1 = (tid>>1)&31, hw = tid&1) sums regions
//   hw*8 .. hw*8+7 at slot (s1*32+l1), writes result in-place into region
//   hw*8 (sole reader of every touched location -> no intra-stage hazard).
// Stage-2 (128 threads): gate[g] = region0[slot] + region8[slot].
// ---------------------------------------------------------------------------
__global__ __launch_bounds__(512, 1) void lstm_scan(const float* __restrict__ Wh,
                                                    const float* __restrict__ bh,
                                                    float* __restrict__ out) {
    extern __shared__ float smem[];
    float* w_s = smem;                        // JPB * WJ floats
    float* h_s = smem + JPB * WJ;             // 512*32 floats (+ partials)

    const int dir = blockIdx.x >> 6;
    const int sub = blockIdx.x & 63;
    const int j0 = sub * JPB;
    const int tid = threadIdx.x;
    const int w = tid >> 5;        // warp 0..15 == k-sixteenth
    const int lane = tid & 31;
    const int j = lane >> 2;       // 0..7
    const int bg = lane & 3;       // 0..3
    const int b0 = bg * 8;
    const int k0 = w * 32;

    // Load Wh tile once, duplicated (w,w) pairs per gate.
    for (int i = tid; i < JPB * 512; i += 512) {
        int j2 = i >> 9;
        int k = i & 511;
        float w0 = Wh[(size_t)(0 * Hsz + j0 + j2) * Hsz + k];
        float w1 = Wh[(size_t)(1 * Hsz + j0 + j2) * Hsz + k];
        float w2 = Wh[(size_t)(2 * Hsz + j0 + j2) * Hsz + k];
        float w3 = Wh[(size_t)(3 * Hsz + j0 + j2) * Hsz + k];
        float* d = &w_s[(size_t)j2 * WJ + k * 8];
        *(float4*)&d[0] = make_float4(w0, w0, w1, w1);
        *(float4*)&d[4] = make_float4(w2, w2, w3, w3);
    }

    // Finalize-thread statics (tid < 128).
    const int j_f = tid >> 4;
    const int bp = tid & 15;
    const int bg_f = bp >> 2;
    const int pp = bp & 3;
    const int bph = pp >> 1;
    const int sel = pp & 1;
    const int L = j_f * 4 + bg_f;
    float bh_g[4];
    if (tid < 128) {
#pragma unroll
        for (int g = 0; g < 4; g++) bh_g[g] = bh[g * Hsz + j0 + j_f];
    }
    float cst[2] = {0.f, 0.f};

    // Stage-1 statics.
    const int s1 = tid >> 6;            // 0..7
    const int l1 = (tid >> 1) & 31;     // 0..31
    const int hw = tid & 1;             // 0..1
    const int slot4 = (s1 * 32 + l1) * 4;  // float offset of this ull2 slot

    const unsigned* my_flag =
        (lane < 4) ? &g_pflag[dir][4 * w + lane][0] : nullptr;
    unsigned* own_flag = &g_pflag[dir][sub][0];
    __syncthreads();

    for (int t = 0; t < Tsz; t++) {
        const int te = dir ? (Tsz - 1 - t) : t;

        // ---- Warp-autonomous flag-gated staging of own k-slice ---------
        {
            bool ready = (lane >= 4);
            if (!ready) ready = (ld_acquire_gpu(my_flag) >= (unsigned)t);
            while (!__all_sync(0xffffffffu, ready)) {
                if (!ready) ready = (ld_acquire_gpu(my_flag) >= (unsigned)t);
            }
            const float4* src =
                (const float4*)&g_h[dir][t & 1][0] + 256 * w;
            float4* dst = (float4*)(h_s + 1024 * w);
#pragma unroll
            for (int i = 0; i < 8; i++)
                dst[lane + 32 * i] = __ldcg(src + lane + 32 * i);
        }

        // ---- k-sixteenth GEMV: 1j x 4g x 8b ----------------------------
        unsigned long long acc[4][4];
#pragma unroll
        for (int g = 0; g < 4; g++)
#pragma unroll
            for (int q = 0; q < 4; q++) acc[g][q] = 0ull;

        const ulonglong2* wp2 =
            (const ulonglong2*)(w_s + (size_t)j * WJ + k0 * 8);
        const ulonglong2* hp2 = (const ulonglong2*)(h_s + k0 * 32 + b0);
#pragma unroll 4
        for (int kk = 0; kk < 32; kk++) {
            ulonglong2 hAB = hp2[0];
            ulonglong2 hCD = hp2[1];
            ulonglong2 wd01 = wp2[0];
            ulonglong2 wd23 = wp2[1];
            acc[0][0] = fma2(wd01.x, hAB.x, acc[0][0]);
            acc[0][1] = fma2(wd01.x, hAB.y, acc[0][1]);
            acc[0][2] = fma2(wd01.x, hCD.x, acc[0][2]);
            acc[0][3] = fma2(wd01.x, hCD.y, acc[0][3]);
            acc[1][0] = fma2(wd01.y, hAB.x, acc[1][0]);
            acc[1][1] = fma2(wd01.y, hAB.y, acc[1][1]);
            acc[1][2] = fma2(wd01.y, hCD.x, acc[1][2]);
            acc[1][3] = fma2(wd01.y, hCD.y, acc[1][3]);
            acc[2][0] = fma2(wd23.x, hAB.x, acc[2][0]);
            acc[2][1] = fma2(wd23.x, hAB.y, acc[2][1]);
            acc[2][2] = fma2(wd23.x, hCD.x, acc[2][2]);
            acc[2][3] = fma2(wd23.x, hCD.y, acc[2][3]);
            acc[3][0] = fma2(wd23.y, hAB.x, acc[3][0]);
            acc[3][1] = fma2(wd23.y, hAB.y, acc[3][1]);
            acc[3][2] = fma2(wd23.y, hCD.x, acc[3][2]);
            acc[3][3] = fma2(wd23.y, hCD.y, acc[3][3]);
            wp2 += 2;
            hp2 += 8;
        }

        // ---- Dump partials into own region (warp-local, no sync) -------
        {
            ulonglong2* rd = (ulonglong2*)(h_s + 1024 * w);
#pragma unroll
            for (int g = 0; g < 4; g++) {
                rd[(g * 2 + 0) * 32 + lane] =
                    make_ulonglong2(acc[g][0], acc[g][1]);
                rd[(g * 2 + 1) * 32 + lane] =
                    make_ulonglong2(acc[g][2], acc[g][3]);
            }
        }

        // gx prefetch for finalize threads (in flight across the syncs).
        float gxr[8];
        if (tid < 128) {
#pragma unroll
            for (int g = 0; g < 4; g++) {
                const float* gp =
                    g_gx + ((size_t)(2 * bp) * Tsz + te) * G4 + g * Hsz +
                    j0 + j_f;
                gxr[g * 2 + 0] = __ldcg(gp);
                gxr[g * 2 + 1] = __ldcg(gp + (size_t)Tsz * G4);
            }
        }
        __syncthreads();   // all partials visible

        // ---- Stage-1: 512 threads fold 16 partial regions into 2 -------
        {
            const float* base = h_s + hw * 8192 + slot4;
            ulonglong2 v0 = *(const ulonglong2*)base;
            unsigned long long sx = v0.x, sy = v0.y;
#pragma unroll
            for (int r = 1; r < 8; r++) {
                ulonglong2 vr = *(const ulonglong2*)(base + r * 1024);
                sx = add2(sx, vr.x);
                sy = add2(sy, vr.y);
            }
            *(ulonglong2*)(h_s + hw * 8192 + slot4) =
                make_ulonglong2(sx, sy);
        }
        __syncthreads();   // stage-1 results visible

        // ---- Stage-2 + cell update (128 threads) -----------------------
        float hv[2];
        if (tid < 128) {
            unsigned long long gate[4];
#pragma unroll
            for (int g = 0; g < 4; g++) {
                const int off = ((g * 2 + bph) * 32 + L) * 4 + sel * 2;
                gate[g] = add2(*(const unsigned long long*)&h_s[off],
                               *(const unsigned long long*)&h_s[8192 + off]);
            }
            float2 gi2 = unpack2(gate[0]);
            float2 gf2 = unpack2(gate[1]);
            float2 gg2 = unpack2(gate[2]);
            float2 go2 = unpack2(gate[3]);
            float gi[2] = {gi2.x, gi2.y};
            float gf[2] = {gf2.x, gf2.y};
            float gg[2] = {gg2.x, gg2.y};
            float go[2] = {go2.x, go2.y};
#pragma unroll
            for (int bi = 0; bi < 2; bi++) {
                float vi = gi[bi] + gxr[0 * 2 + bi] + bh_g[0];
                float vf = gf[bi] + gxr[1 * 2 + bi] + bh_g[1];
                float vg = gg[bi] + gxr[2 * 2 + bi] + bh_g[2];
                float vo = go[bi] + gxr[3 * 2 + bi] + bh_g[3];
                float it = fast_sigmoid(vi);
                float ft = fast_sigmoid(vf);
                float gt = fast_tanh(vg);
                float ot = fast_sigmoid(vo);
                cst[bi] = cst[bi] * ft + it * gt;
                hv[bi] = ot * fast_tanh(cst[bi]);
            }
            // Publish h(t+1) slice (critical path).
            *(float2*)&g_h[dir][(t + 1) & 1][(j0 + j_f) * 32 + 2 * bp] =
                make_float2(hv[0], hv[1]);
        }

        __syncthreads();   // h slice stored by all owners before flag
        if (tid == 0) {
            __threadfence();
            st_relaxed_gpu(own_flag, (unsigned)(t + 1));
        }

        // ---- Deferred output stores (off the inter-block path) ---------
        if (tid < 128) {
            out[((size_t)(2 * bp) * Tsz + t) * (2 * Hsz) + dir * Hsz + j0 +
                j_f] = hv[0];
            out[((size_t)(2 * bp + 1) * Tsz + t) * (2 * Hsz) + dir * Hsz +
                j0 + j_f] = hv[1];
        }
    }
}

// ---------------------------------------------------------------------------
extern "C" void kernel_launch(void* const* d_in, const int* in_sizes, int n_in,
                              void* d_out, int out_size) {
    const float* x = (const float*)d_in[0];   // (32,512,512)
    const float* Wx = (const float*)d_in[1];  // (2048,512)
    const float* bx = (const float*)d_in[2];  // (2048)
    const float* Wh = (const float*)d_in[3];  // (2048,512)
    const float* bh = (const float*)d_in[4];  // (2048)
    float* out = (float*)d_out;               // (32,512,1024)

    void* p_h = nullptr;
    void* p_flag = nullptr;
    cudaGetSymbolAddress(&p_h, g_h);
    cudaGetSymbolAddress(&p_flag, g_pflag);
    cudaMemsetAsync(p_h, 0, sizeof(g_h), 0);
    cudaMemsetAsync(p_flag, 0, sizeof(g_pflag), 0);

    // Phase A: input projection GEMM (128x128 tiles, SIMT f32x2).
    dim3 grid(G4 / 128, (Bsz * Tsz) / 128);
    gemm_gx<<<grid, 256>>>(x, Wx, bx);

    // Phase B: persistent scan.
    const int smem_bytes = (JPB * WJ + Hsz * Bsz) * (int)sizeof(float);
    cudaFuncSetAttribute(lstm_scan, cudaFuncAttributeMaxDynamicSharedMemorySize,
                         smem_bytes);
    lstm_scan<<<2 * NBLK_DIR, 512, smem_bytes>>>(Wh, bh, out);
}